// round 6
// baseline (speedup 1.0000x reference)
#include <cuda_runtime.h>
#include <cuda_bf16.h>
#include <cstdint>

// SegmentMM: out[i] = A[i] @ B_eff[segA[i]]
// A:[131072,64] f32, B:[128,64,64] f32, segA int32 sorted, segB int32 perm.
// bf16 3-split (Ah*Bh + Ah*Bl + Al*Bh) on HMMA m16n8k16.
// R6: A fragments loaded directly from gmem + register split (no smem A);
// B prefetched via cp.async before A work; ldmatrix x4.trans for B.

#define S_SEG 128

// Pre-split B, SW128-swizzled tile images, indexed by segment LABEL.
__device__ __align__(16) unsigned char d_Bh[S_SEG * 8192];
__device__ __align__(16) unsigned char d_Bl[S_SEG * 8192];

__device__ __forceinline__ uint32_t sw128(uint32_t off) {
    return off ^ ((off >> 3) & 0x70);
}

__device__ __forceinline__ void cvt_split4(float4 v, uint2& hi, uint2& lo) {
    __nv_bfloat162 h01 = __floats2bfloat162_rn(v.x, v.y);
    __nv_bfloat162 h23 = __floats2bfloat162_rn(v.z, v.w);
    float rx = v.x - __bfloat162float(h01.x);
    float ry = v.y - __bfloat162float(h01.y);
    float rz = v.z - __bfloat162float(h23.x);
    float rw = v.w - __bfloat162float(h23.y);
    __nv_bfloat162 l01 = __floats2bfloat162_rn(rx, ry);
    __nv_bfloat162 l23 = __floats2bfloat162_rn(rz, rw);
    hi = make_uint2(*(uint32_t*)&h01, *(uint32_t*)&h23);
    lo = make_uint2(*(uint32_t*)&l01, *(uint32_t*)&l23);
}

// split a float2 into bf16x2 hi and bf16x2 lo (packed u32)
__device__ __forceinline__ void cvt_split2(float2 v, uint32_t& hi, uint32_t& lo) {
    __nv_bfloat162 h = __floats2bfloat162_rn(v.x, v.y);
    float rx = v.x - __bfloat162float(h.x);
    float ry = v.y - __bfloat162float(h.y);
    __nv_bfloat162 l = __floats2bfloat162_rn(rx, ry);
    hi = *(uint32_t*)&h;
    lo = *(uint32_t*)&l;
}

// ---- B pre-split kernel: block j converts B[j] -> d_Bh/d_Bl[segB[j]] ----
__global__ __launch_bounds__(256)
void presplit_B_kernel(const float* __restrict__ B,
                       const int* __restrict__ segB)
{
    const int j = blockIdx.x;
    const int s = segB[j];
    const int tid = threadIdx.x;
    const float4* B4 = (const float4*)(B + (size_t)j * 4096);
    unsigned char* bh = d_Bh + (size_t)s * 8192;
    unsigned char* bl = d_Bl + (size_t)s * 8192;
    #pragma unroll
    for (int it = 0; it < 4; ++it) {
        int i = it * 256 + tid;          // 0..1023 float4s
        float4 v = B4[i];
        int k = i >> 4, mq = i & 15;
        uint32_t sw = sw128((uint32_t)(k * 128 + mq * 8));
        uint2 hi, lo;
        cvt_split4(v, hi, lo);
        *(uint2*)(bh + sw) = hi;
        *(uint2*)(bl + sw) = lo;
    }
}

// ---- main kernel ----
#define SM_BH 0          // 64 k-rows x 64 bf16, SW128   8KB
#define SM_BL 8192       //                               8KB
#define SMEM_TOTAL 16384

__device__ __forceinline__ uint32_t smem_u32(const void* p) {
    uint32_t a;
    asm("{ .reg .u64 t; cvta.to.shared.u64 t, %1; cvt.u32.u64 %0, t; }"
        : "=r"(a) : "l"(p));
    return a;
}
__device__ __forceinline__ void ldsm_x4t(uint32_t& r0, uint32_t& r1,
                                         uint32_t& r2, uint32_t& r3, uint32_t a) {
    asm volatile("ldmatrix.sync.aligned.m8n8.x4.trans.shared.b16 {%0,%1,%2,%3}, [%4];"
                 : "=r"(r0), "=r"(r1), "=r"(r2), "=r"(r3) : "r"(a));
}
__device__ __forceinline__ void mma16816(float* d, const uint32_t* a,
                                         uint32_t b0, uint32_t b1) {
    asm volatile(
        "mma.sync.aligned.m16n8k16.row.col.f32.bf16.bf16.f32 "
        "{%0,%1,%2,%3}, {%4,%5,%6,%7}, {%8,%9}, {%0,%1,%2,%3};"
        : "+f"(d[0]), "+f"(d[1]), "+f"(d[2]), "+f"(d[3])
        : "r"(a[0]), "r"(a[1]), "r"(a[2]), "r"(a[3]), "r"(b0), "r"(b1));
}
#define CP_ASYNC16(dst, src)                                                   \
    asm volatile("cp.async.cg.shared.global [%0], [%1], 16;"                   \
                 :: "r"(dst), "l"(src) : "memory")
#define CP_COMMIT  asm volatile("cp.async.commit_group;" ::: "memory")
#define CP_WAIT0   asm volatile("cp.async.wait_group 0;" ::: "memory")

__global__ __launch_bounds__(128, 5)
void segmm_hmma_kernel(const float* __restrict__ A,
                       const int* __restrict__ segA,
                       float* __restrict__ out)
{
    __shared__ __align__(128) unsigned char smem[SMEM_TOTAL];
    const uint32_t sb  = smem_u32(smem);
    const int tid  = threadIdx.x;
    const int w    = tid >> 5;          // warp 0..3, owns rows w*16..w*16+15
    const int lane = tid & 31;
    const int r0   = blockIdx.x * 64;

    // per-thread output rows (c-fragment layout) and their segments
    const int rA = w * 16 + (lane >> 2);
    const int rB = rA + 8;
    const int cb = (lane & 3) * 2;
    const int segLoRow = segA[r0 + rA];
    const int segHiRow = segA[r0 + rB];
    const int s_lo = segA[r0];
    const int s_hi = segA[r0 + 63];

    // ---- prefetch B(s_lo) via cp.async (flies under A load/convert) ----
    {
        const unsigned char* gh = d_Bh + (size_t)s_lo * 8192;
        const unsigned char* gl = d_Bl + (size_t)s_lo * 8192;
        #pragma unroll
        for (int it = 0; it < 4; ++it) {
            uint32_t off = (uint32_t)(it * 128 + tid) * 16;
            CP_ASYNC16(sb + SM_BH + off, gh + off);
            CP_ASYNC16(sb + SM_BL + off, gl + off);
        }
        CP_COMMIT;
    }

    // ---- load A fragments directly from gmem, split in registers ----
    // m16n8k16 A frag: a0={rA, c,c+1} a1={rB, c,c+1} a2={rA, c+8,c+9} a3={rB,...}
    uint32_t ahf[4][4], alf[4][4];
    {
        const float* pA = A + (size_t)(r0 + rA) * 64 + cb;
        const float* pB = A + (size_t)(r0 + rB) * 64 + cb;
        #pragma unroll
        for (int kk = 0; kk < 4; ++kk) {
            float2 v0 = *(const float2*)(pA + kk * 16);
            float2 v1 = *(const float2*)(pB + kk * 16);
            float2 v2 = *(const float2*)(pA + kk * 16 + 8);
            float2 v3 = *(const float2*)(pB + kk * 16 + 8);
            cvt_split2(v0, ahf[kk][0], alf[kk][0]);
            cvt_split2(v1, ahf[kk][1], alf[kk][1]);
            cvt_split2(v2, ahf[kk][2], alf[kk][2]);
            cvt_split2(v3, ahf[kk][3], alf[kk][3]);
        }
    }

    CP_WAIT0;
    __syncthreads();    // B tile visible to all warps

    // B ldmatrix x4.trans lane address components:
    // lanes 0-15 -> ntile ntp*2, lanes 16-31 -> ntile ntp*2+1; row = lane&15
    const uint32_t b_row = (uint32_t)(lane & 15);
    const uint32_t b_nt  = (uint32_t)(lane >> 4);   // 0 or 1

    for (int s = s_lo; s <= s_hi; ++s) {
        if (s > s_lo) {
            __syncthreads();   // everyone done reading previous B
            const unsigned char* gh = d_Bh + (size_t)s * 8192;
            const unsigned char* gl = d_Bl + (size_t)s * 8192;
            #pragma unroll
            for (int it = 0; it < 4; ++it) {
                uint32_t off = (uint32_t)(it * 128 + tid) * 16;
                CP_ASYNC16(sb + SM_BH + off, gh + off);
                CP_ASYNC16(sb + SM_BL + off, gl + off);
            }
            CP_COMMIT;
            CP_WAIT0;
            __syncthreads();
        }

        // skip warps with no row in this segment
        bool okA = (segLoRow == s);
        bool okB = (segHiRow == s);
        if (__ballot_sync(0xffffffffu, okA || okB) == 0u) continue;

        // ---- compute: 4 ksteps x 4 ntile-pairs x (2 ldsm + 6 mma) ----
        float acc[8][4];
        #pragma unroll
        for (int nt = 0; nt < 8; ++nt)
            #pragma unroll
            for (int q = 0; q < 4; ++q) acc[nt][q] = 0.f;

        #pragma unroll
        for (int kk = 0; kk < 4; ++kk) {
            uint32_t roff = ((uint32_t)(kk * 16) + b_row) * 128;
            #pragma unroll
            for (int ntp = 0; ntp < 4; ++ntp) {
                uint32_t sw = sw128(roff + ((uint32_t)(ntp * 2) + b_nt) * 16);
                uint32_t bh0, bh1, bh2, bh3, bl0, bl1, bl2, bl3;
                ldsm_x4t(bh0, bh1, bh2, bh3, sb + SM_BH + sw);
                ldsm_x4t(bl0, bl1, bl2, bl3, sb + SM_BL + sw);
                mma16816(acc[ntp * 2],     ahf[kk], bh0, bh1);
                mma16816(acc[ntp * 2],     ahf[kk], bl0, bl1);
                mma16816(acc[ntp * 2],     alf[kk], bh0, bh1);
                mma16816(acc[ntp * 2 + 1], ahf[kk], bh2, bh3);
                mma16816(acc[ntp * 2 + 1], ahf[kk], bl2, bl3);
                mma16816(acc[ntp * 2 + 1], alf[kk], bh2, bh3);
            }
        }

        // ---- store rows belonging to segment s ----
        float* orA = out + (size_t)(r0 + rA) * 64 + cb;
        float* orB = out + (size_t)(r0 + rB) * 64 + cb;
        #pragma unroll
        for (int nt = 0; nt < 8; ++nt) {
            if (okA) *(float2*)(orA + nt * 8) = make_float2(acc[nt][0], acc[nt][1]);
            if (okB) *(float2*)(orB + nt * 8) = make_float2(acc[nt][2], acc[nt][3]);
        }
    }
}

extern "C" void kernel_launch(void* const* d_in, const int* in_sizes, int n_in,
                              void* d_out, int out_size) {
    const float* A    = (const float*)d_in[0];
    const float* B    = (const float*)d_in[1];
    const int*   segA = (const int*)d_in[2];
    const int*   segB = (const int*)d_in[3];
    float* out = (float*)d_out;

    const int N = in_sizes[0] / 64;      // 131072
    const int S = in_sizes[3];           // 128

    presplit_B_kernel<<<S, 256>>>(B, segB);
    segmm_hmma_kernel<<<N / 64, 128>>>(A, segA, out);
}

// round 7
// speedup vs baseline: 1.1936x; 1.1936x over previous
#include <cuda_runtime.h>
#include <cuda_bf16.h>
#include <cstdint>

// SegmentMM: out[i] = A[i] @ B_eff[segA[i]]
// A:[131072,64] f32, B:[128,64,64] f32, segA int32 sorted, segB int32 perm.
// bf16 3-split (Ah*Bh + Ah*Bl + Al*Bh) on HMMA m16n8k16.
// R7: A staged raw f32 via cp.async (padded rows), fragments gathered by
// LDS.64 + register split; B (presplit bf16) prefetched in the same cp.async
// group -> single wait covers all gmem latency. x4.trans for B ldmatrix.

#define S_SEG 128

// Pre-split B, SW128-swizzled tile images, indexed by segment LABEL.
__device__ __align__(16) unsigned char d_Bh[S_SEG * 8192];
__device__ __align__(16) unsigned char d_Bl[S_SEG * 8192];

__device__ __forceinline__ uint32_t sw128(uint32_t off) {
    return off ^ ((off >> 3) & 0x70);
}

__device__ __forceinline__ void cvt_split4(float4 v, uint2& hi, uint2& lo) {
    __nv_bfloat162 h01 = __floats2bfloat162_rn(v.x, v.y);
    __nv_bfloat162 h23 = __floats2bfloat162_rn(v.z, v.w);
    float rx = v.x - __bfloat162float(h01.x);
    float ry = v.y - __bfloat162float(h01.y);
    float rz = v.z - __bfloat162float(h23.x);
    float rw = v.w - __bfloat162float(h23.y);
    __nv_bfloat162 l01 = __floats2bfloat162_rn(rx, ry);
    __nv_bfloat162 l23 = __floats2bfloat162_rn(rz, rw);
    hi = make_uint2(*(uint32_t*)&h01, *(uint32_t*)&h23);
    lo = make_uint2(*(uint32_t*)&l01, *(uint32_t*)&l23);
}

__device__ __forceinline__ void cvt_split2(float2 v, uint32_t& hi, uint32_t& lo) {
    __nv_bfloat162 h = __floats2bfloat162_rn(v.x, v.y);
    float rx = v.x - __bfloat162float(h.x);
    float ry = v.y - __bfloat162float(h.y);
    __nv_bfloat162 l = __floats2bfloat162_rn(rx, ry);
    hi = *(uint32_t*)&h;
    lo = *(uint32_t*)&l;
}

// ---- B pre-split kernel: block j converts B[j] -> d_Bh/d_Bl[segB[j]] ----
__global__ __launch_bounds__(256)
void presplit_B_kernel(const float* __restrict__ B,
                       const int* __restrict__ segB)
{
    const int j = blockIdx.x;
    const int s = segB[j];
    const int tid = threadIdx.x;
    const float4* B4 = (const float4*)(B + (size_t)j * 4096);
    unsigned char* bh = d_Bh + (size_t)s * 8192;
    unsigned char* bl = d_Bl + (size_t)s * 8192;
    #pragma unroll
    for (int it = 0; it < 4; ++it) {
        int i = it * 256 + tid;          // 0..1023 float4s
        float4 v = B4[i];
        int k = i >> 4, mq = i & 15;
        uint32_t sw = sw128((uint32_t)(k * 128 + mq * 8));
        uint2 hi, lo;
        cvt_split4(v, hi, lo);
        *(uint2*)(bh + sw) = hi;
        *(uint2*)(bl + sw) = lo;
    }
}

// ---- main kernel ----
// smem: A f32 64 rows x 68 floats (272B pitch) = 17408B, then Bh/Bl SW128.
#define A_PITCH_B 272
#define SM_AF  0
#define SM_BH  17408
#define SM_BL  (17408 + 8192)
#define SMEM_TOTAL (17408 + 16384)

__device__ __forceinline__ uint32_t smem_u32(const void* p) {
    uint32_t a;
    asm("{ .reg .u64 t; cvta.to.shared.u64 t, %1; cvt.u32.u64 %0, t; }"
        : "=r"(a) : "l"(p));
    return a;
}
__device__ __forceinline__ void ldsm_x4t(uint32_t& r0, uint32_t& r1,
                                         uint32_t& r2, uint32_t& r3, uint32_t a) {
    asm volatile("ldmatrix.sync.aligned.m8n8.x4.trans.shared.b16 {%0,%1,%2,%3}, [%4];"
                 : "=r"(r0), "=r"(r1), "=r"(r2), "=r"(r3) : "r"(a));
}
__device__ __forceinline__ void mma16816(float* d, const uint32_t* a,
                                         uint32_t b0, uint32_t b1) {
    asm volatile(
        "mma.sync.aligned.m16n8k16.row.col.f32.bf16.bf16.f32 "
        "{%0,%1,%2,%3}, {%4,%5,%6,%7}, {%8,%9}, {%0,%1,%2,%3};"
        : "+f"(d[0]), "+f"(d[1]), "+f"(d[2]), "+f"(d[3])
        : "r"(a[0]), "r"(a[1]), "r"(a[2]), "r"(a[3]), "r"(b0), "r"(b1));
}
#define CP_ASYNC16(dst, src)                                                   \
    asm volatile("cp.async.cg.shared.global [%0], [%1], 16;"                   \
                 :: "r"(dst), "l"(src) : "memory")
#define CP_COMMIT  asm volatile("cp.async.commit_group;" ::: "memory")
#define CP_WAIT0   asm volatile("cp.async.wait_group 0;" ::: "memory")

__global__ __launch_bounds__(128, 5)
void segmm_hmma_kernel(const float* __restrict__ A,
                       const int* __restrict__ segA,
                       float* __restrict__ out)
{
    __shared__ __align__(128) unsigned char smem[SMEM_TOTAL];
    const uint32_t sb  = smem_u32(smem);
    const int tid  = threadIdx.x;
    const int w    = tid >> 5;          // warp 0..3, owns rows w*16..w*16+15
    const int lane = tid & 31;
    const int r0   = blockIdx.x * 64;

    const int rA = w * 16 + (lane >> 2);
    const int rB = rA + 8;
    const int cb = (lane & 3) * 2;      // float column base
    const int segLoRow = segA[r0 + rA];
    const int segHiRow = segA[r0 + rB];
    const int s_lo = segA[r0];
    const int s_hi = segA[r0 + 63];

    // ---- cp.async: A f32 tile + B(s_lo) presplit, one group, one wait ----
    {
        const unsigned char* gA = (const unsigned char*)(A + (size_t)r0 * 64);
        #pragma unroll
        for (int it = 0; it < 8; ++it) {
            int i = it * 128 + tid;          // 0..1023 16B-chunks
            int r = i >> 4, c = i & 15;
            CP_ASYNC16(sb + SM_AF + (uint32_t)(r * A_PITCH_B + c * 16),
                       gA + (size_t)r * 256 + c * 16);
        }
        const unsigned char* gh = d_Bh + (size_t)s_lo * 8192;
        const unsigned char* gl = d_Bl + (size_t)s_lo * 8192;
        #pragma unroll
        for (int it = 0; it < 4; ++it) {
            uint32_t off = (uint32_t)(it * 128 + tid) * 16;
            CP_ASYNC16(sb + SM_BH + off, gh + off);
            CP_ASYNC16(sb + SM_BL + off, gl + off);
        }
        CP_COMMIT;
    }
    CP_WAIT0;
    __syncthreads();

    // A fragment smem byte addresses (f32, padded pitch)
    const uint32_t aA = sb + SM_AF + (uint32_t)rA * A_PITCH_B + (uint32_t)cb * 4;
    const uint32_t aB = sb + SM_AF + (uint32_t)rB * A_PITCH_B + (uint32_t)cb * 4;

    const uint32_t b_row = (uint32_t)(lane & 15);
    const uint32_t b_nt  = (uint32_t)(lane >> 4);   // 0 or 1

    for (int s = s_lo; s <= s_hi; ++s) {
        if (s > s_lo) {
            __syncthreads();   // everyone done reading previous B
            const unsigned char* gh = d_Bh + (size_t)s * 8192;
            const unsigned char* gl = d_Bl + (size_t)s * 8192;
            #pragma unroll
            for (int it = 0; it < 4; ++it) {
                uint32_t off = (uint32_t)(it * 128 + tid) * 16;
                CP_ASYNC16(sb + SM_BH + off, gh + off);
                CP_ASYNC16(sb + SM_BL + off, gl + off);
            }
            CP_COMMIT;
            CP_WAIT0;
            __syncthreads();
        }

        bool okA = (segLoRow == s);
        bool okB = (segHiRow == s);
        if (__ballot_sync(0xffffffffu, okA || okB) == 0u) continue;

        float acc[8][4];
        #pragma unroll
        for (int nt = 0; nt < 8; ++nt)
            #pragma unroll
            for (int q = 0; q < 4; ++q) acc[nt][q] = 0.f;

        #pragma unroll
        for (int kk = 0; kk < 4; ++kk) {
            // gather A fragments from f32 smem, split in registers
            float2 v0, v1, v2, v3;
            asm volatile("ld.shared.v2.f32 {%0,%1}, [%2];"
                         : "=f"(v0.x), "=f"(v0.y) : "r"(aA + kk * 64));
            asm volatile("ld.shared.v2.f32 {%0,%1}, [%2];"
                         : "=f"(v1.x), "=f"(v1.y) : "r"(aB + kk * 64));
            asm volatile("ld.shared.v2.f32 {%0,%1}, [%2];"
                         : "=f"(v2.x), "=f"(v2.y) : "r"(aA + kk * 64 + 32));
            asm volatile("ld.shared.v2.f32 {%0,%1}, [%2];"
                         : "=f"(v3.x), "=f"(v3.y) : "r"(aB + kk * 64 + 32));
            uint32_t ahf[4], alf[4];
            cvt_split2(v0, ahf[0], alf[0]);
            cvt_split2(v1, ahf[1], alf[1]);
            cvt_split2(v2, ahf[2], alf[2]);
            cvt_split2(v3, ahf[3], alf[3]);

            uint32_t roff = ((uint32_t)(kk * 16) + b_row) * 128;
            #pragma unroll
            for (int ntp = 0; ntp < 4; ++ntp) {
                uint32_t sw = sw128(roff + ((uint32_t)(ntp * 2) + b_nt) * 16);
                uint32_t bh0, bh1, bh2, bh3, bl0, bl1, bl2, bl3;
                ldsm_x4t(bh0, bh1, bh2, bh3, sb + SM_BH + sw);
                ldsm_x4t(bl0, bl1, bl2, bl3, sb + SM_BL + sw);
                mma16816(acc[ntp * 2],     ahf, bh0, bh1);
                mma16816(acc[ntp * 2],     ahf, bl0, bl1);
                mma16816(acc[ntp * 2],     alf, bh0, bh1);
                mma16816(acc[ntp * 2 + 1], ahf, bh2, bh3);
                mma16816(acc[ntp * 2 + 1], ahf, bl2, bl3);
                mma16816(acc[ntp * 2 + 1], alf, bh2, bh3);
            }
        }

        float* orA = out + (size_t)(r0 + rA) * 64 + cb;
        float* orB = out + (size_t)(r0 + rB) * 64 + cb;
        #pragma unroll
        for (int nt = 0; nt < 8; ++nt) {
            if (okA) *(float2*)(orA + nt * 8) = make_float2(acc[nt][0], acc[nt][1]);
            if (okB) *(float2*)(orB + nt * 8) = make_float2(acc[nt][2], acc[nt][3]);
        }
    }
}

extern "C" void kernel_launch(void* const* d_in, const int* in_sizes, int n_in,
                              void* d_out, int out_size) {
    const float* A    = (const float*)d_in[0];
    const float* B    = (const float*)d_in[1];
    const int*   segA = (const int*)d_in[2];
    const int*   segB = (const int*)d_in[3];
    float* out = (float*)d_out;

    const int N = in_sizes[0] / 64;      // 131072
    const int S = in_sizes[3];           // 128

    presplit_B_kernel<<<S, 256>>>(B, segB);
    segmm_hmma_kernel<<<N / 64, 128>>>(A, segA, out);
}